// round 17
// baseline (speedup 1.0000x reference)
#include <cuda_runtime.h>

// WinCorr: out[s=(i,j,k), d,h,w] = scale * sum_c fixed[c,d,h,w] * moving[c, d+i-1, h+j-1, w+k-1]
// fixed/moving (1,32,96,96,96) f32; out (1,27,96,96,96) f32; zero padding.
// R15 tile (3 h-outputs/thread, 4 blocks/SM) with channel-PAIR pipeline steps:
// NSTAGE=6, one wait+barrier+commit per 2 channels.

#define CC   32
#define DD   96
#define HH   96
#define WW   96
#define HWSZ (HH * WW)
#define DHW  (DD * HWSZ)

#define WT   32
#define HT   12                // 4 warps x 3 h-rows
#define SM_D 3
#define SM_H (HT + 2)          // 14
#define ROWS (SM_D * SM_H)     // 42
#define RW   40                // row width words (160B; gw in [w0-4, w0+36))
#define TILE_W (ROWS * RW)     // 1680 words
#define TILE_B (TILE_W * 4)    // 6720 bytes
#define NSTAGE 6               // 6 channel-stages = 3 pairs
#define QPR  10                // 16B chunks per row
#define TOTOPS (ROWS * QPR)    // 420
#define NOPS 4                 // ceil(420/128)
#define NTHR 128
#define NPAIR (CC / 2)         // 16

__device__ __forceinline__ void cp_async16(unsigned s, const void* g) {
    asm volatile("cp.async.cg.shared.global [%0], [%1], 16;\n" :: "r"(s), "l"(g));
}
__device__ __forceinline__ void cp_commit() {
    asm volatile("cp.async.commit_group;\n" ::: "memory");
}
__device__ __forceinline__ void cp_wait1() {
    asm volatile("cp.async.wait_group 1;\n" ::: "memory");
}

__global__ __launch_bounds__(NTHR, 4)
void wincorr_kernel(const float* __restrict__ fx,
                    const float* __restrict__ mv,
                    float* __restrict__ out)
{
    __shared__ float sm[NSTAGE * TILE_W];   // 40320 B -> 4 blocks/SM

    const int tx  = threadIdx.x;            // lane -> w
    const int ty  = threadIdx.y;            // warp 0..3 -> 3-row h strip
    const int tid = ty * 32 + tx;

    const int w0 = blockIdx.x * WT;
    const int h0 = blockIdx.y * HT;
    const int d  = blockIdx.z;

    const int h = h0 + 3 * ty;              // outputs h..h+2
    const int w = w0 + tx;

    // pre-zero all stages once: OOB halo slots stay zero for the whole kernel
    for (int i = tid; i < NSTAGE * TILE_W; i += NTHR) sm[i] = 0.f;

    // ---- per-thread c-invariant cp.async descriptors ----
    int      srcB[NOPS];   // byte offset within a moving channel; -1 = skip
    unsigned db[NOPS];     // byte offset within a stage
    #pragma unroll
    for (int t = 0; t < NOPS; ++t) {
        int o  = tid + NTHR * t;
        int r  = o / QPR;                   // tile row 0..41
        int q  = o - r * QPR;               // chunk 0..9
        int dz = r / SM_H;
        int lh = r - dz * SM_H;
        int gd = d  + dz - 1;
        int gh = h0 + lh - 1;
        int gs = w0 - 4 + 4 * q;
        bool v = (o < TOTOPS) && ((unsigned)gd < DD) && ((unsigned)gh < HH)
                              && (gs >= 0) && (gs + 4 <= WW);
        srcB[t] = v ? (gd * HWSZ + gh * WW + gs) * 4 : -1;
        db[t]   = (unsigned)(r * (RW * 4) + q * 16);
    }

    __syncthreads();   // zeros visible before any cp.async lands

    const unsigned smb = (unsigned)__cvta_generic_to_shared(sm);
    const char* mvb = (const char*)mv;

    // ---- prologue: launch pairs 0 (ch 0,1) and 1 (ch 2,3), one group each ----
    #pragma unroll
    for (int p = 0; p < 2; ++p) {
        #pragma unroll
        for (int half = 0; half < 2; ++half) {
            const int c = 2 * p + half;
            const unsigned sb = smb + (unsigned)(c % NSTAGE) * TILE_B;
            const char* pb = mvb + (size_t)c * (DHW * 4);
            #pragma unroll
            for (int t = 0; t < NOPS; ++t)
                if (srcB[t] >= 0) cp_async16(sb + db[t], pb + srcB[t]);
        }
        cp_commit();
    }

    const float* fp = fx + (size_t)d * HWSZ + (size_t)h * WW + w;
    const float* fq = fp;                   // points at channel to prefetch next
    float fc[3];
    fc[0] = __ldg(fq);
    fc[1] = __ldg(fq + WW);
    fc[2] = __ldg(fq + 2 * WW);

    float acc[81];                          // [lo][dz*9 + jj*3 + kk]
    #pragma unroll
    for (int s = 0; s < 81; ++s) acc[s] = 0.f;

    #pragma unroll 3
    for (int p = 0; p < NPAIR; ++p) {
        cp_wait1();        // pair p resident (pair p+1 may still fly)
        __syncthreads();   // all warps see pair p AND finished reading pair p-1's stages

        // safe now: launch pair p+2 (ch 2p+4, 2p+5) into pair (p-1)'s stages
        if (p + 2 < NPAIR) {
            #pragma unroll
            for (int half = 0; half < 2; ++half) {
                const int c = 2 * p + 4 + half;
                const unsigned sb = smb + (unsigned)(c % NSTAGE) * TILE_B;
                const char* pb = mvb + (size_t)c * (DHW * 4);
                #pragma unroll
                for (int t = 0; t < NOPS; ++t)
                    if (srcB[t] >= 0) cp_async16(sb + db[t], pb + srcB[t]);
            }
        }
        cp_commit();       // unconditional: uniform group count for wait_group 1

        // ---- compute the two channels of pair p ----
        #pragma unroll
        for (int half = 0; half < 2; ++half) {
            const int c = 2 * p + half;

            const float f0 = fc[0], f1 = fc[1], f2 = fc[2];
            if (c + 1 < CC) {               // prefetch fixed for channel c+1
                fq += DHW;
                fc[0] = __ldg(fq);
                fc[1] = __ldg(fq + WW);
                fc[2] = __ldg(fq + 2 * WW);
            }

            // 45 conflict-free LDS [R+imm] + 81 FFMA
            const float* base = sm + (c % NSTAGE) * TILE_W + (3 * ty) * RW + tx + 3;
            #pragma unroll
            for (int dz = 0; dz < 3; ++dz) {
                #pragma unroll
                for (int yy = 0; yy < 5; ++yy) {   // gh = h-1+yy ; jj = yy-lo in [0,2]
                    #pragma unroll
                    for (int kk = 0; kk < 3; ++kk) {
                        const float m = base[(dz * SM_H + yy) * RW + kk];
                        if (yy <= 2)            acc[0 * 27 + dz * 9 + (yy    ) * 3 + kk] += f0 * m;
                        if (yy >= 1 && yy <= 3) acc[1 * 27 + dz * 9 + (yy - 1) * 3 + kk] += f1 * m;
                        if (yy >= 2)            acc[2 * 27 + dz * 9 + (yy - 2) * 3 + kk] += f2 * m;
                    }
                }
            }
        }
    }

    const float scale = 0.17677669529663687f;   // 32^-0.5
    float* op = out + (size_t)d * HWSZ + (size_t)h * WW + w;
    #pragma unroll
    for (int s = 0; s < 27; ++s) {
        #pragma unroll
        for (int lo = 0; lo < 3; ++lo)
            op[(size_t)s * DHW + lo * WW] = acc[lo * 27 + s] * scale;
    }
}

extern "C" void kernel_launch(void* const* d_in, const int* in_sizes, int n_in,
                              void* d_out, int out_size)
{
    const float* fixed  = (const float*)d_in[0];
    const float* moving = (const float*)d_in[1];
    float* out = (float*)d_out;

    dim3 block(32, 4, 1);                    // 128 threads
    dim3 grid(WW / WT, HH / HT, DD);         // (3, 8, 96) = 2304 blocks
    wincorr_kernel<<<grid, block>>>(fixed, moving, out);
}